// round 2
// baseline (speedup 1.0000x reference)
#include <cuda_runtime.h>
#include <math.h>
#include <float.h>

// Problem constants (fixed by the dataset)
#define LL 4
#define BB 256
#define CC 512
#define SS 64
#define NPTS 50000
#define KSEL 21   // k+1 smallest needed

// -------- scratch (static device globals; no runtime allocation) --------
__device__ float g_q[LL * BB * CC];          // 2 MB
__device__ float g_q2[LL * BB];
__device__ float g_b2[LL * NPTS];
__device__ float g_d2[(size_t)LL * BB * NPTS]; // 204.8 MB

// -------- packed f32x2 helpers (Blackwell FFMA2 path) --------
__device__ __forceinline__ unsigned long long pack2(float lo, float hi) {
    unsigned long long d;
    asm("mov.b64 %0, {%1, %2};" : "=l"(d) : "f"(lo), "f"(hi));
    return d;
}
__device__ __forceinline__ void unpack2(unsigned long long x, float& lo, float& hi) {
    asm("mov.b64 {%0, %1}, %2;" : "=f"(lo), "=f"(hi) : "l"(x));
}
__device__ __forceinline__ unsigned long long ffma2(unsigned long long a,
                                                    unsigned long long b,
                                                    unsigned long long c) {
    unsigned long long d;
    asm("fma.rn.f32x2 %0, %1, %2, %3;" : "=l"(d) : "l"(a), "l"(b), "l"(c));
    return d;
}

// ============================================================
// Kernel 1: q[l,b,c] = mean_s feats[l,b,c,s]   (one warp per row of 64)
// ============================================================
__global__ void qmean_kernel(const float* __restrict__ feats) {
    int gw = (blockIdx.x * blockDim.x + threadIdx.x) >> 5;
    int lane = threadIdx.x & 31;
    if (gw >= LL * BB * CC) return;
    const float* p = feats + (size_t)gw * SS;
    float s = p[lane] + p[lane + 32];
    #pragma unroll
    for (int o = 16; o > 0; o >>= 1) s += __shfl_xor_sync(0xFFFFFFFFu, s, o);
    if (lane == 0) g_q[gw] = s * (1.0f / 64.0f);
}

// ============================================================
// Kernel 2: q2[l,b] = sum_c q^2     (one warp per row of 512)
// ============================================================
__global__ void q2_kernel() {
    int gw = (blockIdx.x * blockDim.x + threadIdx.x) >> 5;
    int lane = threadIdx.x & 31;
    if (gw >= LL * BB) return;
    const float* p = g_q + (size_t)gw * CC;
    float s = 0.f;
    #pragma unroll
    for (int j = 0; j < CC / 32; j++) {
        float v = p[lane + 32 * j];
        s = fmaf(v, v, s);
    }
    #pragma unroll
    for (int o = 16; o > 0; o >>= 1) s += __shfl_xor_sync(0xFFFFFFFFu, s, o);
    if (lane == 0) g_q2[gw] = s;
}

// ============================================================
// Kernel 3: b2[l,n] = sum_c bank^2  (one warp per row of 512, float4)
// ============================================================
__global__ void b2_kernel(const float* __restrict__ bank) {
    int gw = (blockIdx.x * blockDim.x + threadIdx.x) >> 5;
    int lane = threadIdx.x & 31;
    if (gw >= LL * NPTS) return;
    const float* p = bank + (size_t)gw * CC;
    float s = 0.f;
    #pragma unroll
    for (int j = 0; j < 4; j++) {
        float4 v = *(const float4*)(p + j * 128 + lane * 4);
        s = fmaf(v.x, v.x, s);
        s = fmaf(v.y, v.y, s);
        s = fmaf(v.z, v.z, s);
        s = fmaf(v.w, v.w, s);
    }
    #pragma unroll
    for (int o = 16; o > 0; o >>= 1) s += __shfl_xor_sync(0xFFFFFFFFu, s, o);
    if (lane == 0) g_b2[gw] = s;
}

// ============================================================
// Kernel 4: fused GEMM + squared-distance epilogue
//   d2[l,b,n] = q2[l,b] + b2[l,n] - 2 * <q[l,b,:], bank[l,n,:]>
//   CTA tile 128x128, BK=16, 256 threads, thread tile 8x8,
//   accumulators packed as f32x2 pairs along M (rows 2i,2i+1).
// ============================================================
#define Bb 128
#define Bn 128
#define Bk 16

__global__ __launch_bounds__(256)
void gemm_d2_kernel(const float* __restrict__ bank) {
    __shared__ float As[Bk][Bb];
    __shared__ float Bs[Bk][Bn];
    __shared__ float q2s[Bb];
    __shared__ float b2s[Bn];

    const int l  = blockIdx.z;
    const int m0 = blockIdx.x * Bb;   // 0 or 128
    const int n0 = blockIdx.y * Bn;   // n tile
    const int nrem = NPTS - n0;       // valid columns in this tile

    const float* Ap = g_q  + ((size_t)l * BB   + m0) * CC;
    const float* Bp = bank + ((size_t)l * NPTS + n0) * CC;

    const int tid = threadIdx.x;
    const int tm = tid >> 4;   // 0..15 -> rows tm*8 .. tm*8+7
    const int tn = tid & 15;   // 0..15 -> cols tn + 16*j, j=0..7

    unsigned long long acc[4][8];
    #pragma unroll
    for (int i = 0; i < 4; i++)
        #pragma unroll
        for (int j = 0; j < 8; j++) acc[i][j] = 0ull;  // 0.0f|0.0f

    for (int k0 = 0; k0 < CC; k0 += Bk) {
        // load A tile (128x16) -> As[k][m]
        #pragma unroll
        for (int i = 0; i < 2; i++) {
            int idx = tid + i * 256;
            int row = idx >> 2;
            int k4  = (idx & 3) << 2;
            float4 v = *(const float4*)(Ap + (size_t)row * CC + k0 + k4);
            As[k4 + 0][row] = v.x;
            As[k4 + 1][row] = v.y;
            As[k4 + 2][row] = v.z;
            As[k4 + 3][row] = v.w;
        }
        // load B tile (128x16) -> Bs[k][n], zero-fill OOB rows
        #pragma unroll
        for (int i = 0; i < 2; i++) {
            int idx = tid + i * 256;
            int row = idx >> 2;
            int k4  = (idx & 3) << 2;
            float4 v = make_float4(0.f, 0.f, 0.f, 0.f);
            if (row < nrem)
                v = *(const float4*)(Bp + (size_t)row * CC + k0 + k4);
            Bs[k4 + 0][row] = v.x;
            Bs[k4 + 1][row] = v.y;
            Bs[k4 + 2][row] = v.z;
            Bs[k4 + 3][row] = v.w;
        }
        __syncthreads();

        #pragma unroll
        for (int kk = 0; kk < Bk; kk++) {
            const unsigned long long* a2 =
                (const unsigned long long*)&As[kk][tm * 8];
            unsigned long long ar[4];
            #pragma unroll
            for (int i = 0; i < 4; i++) ar[i] = a2[i];
            #pragma unroll
            for (int j = 0; j < 8; j++) {
                float bv = Bs[kk][tn + 16 * j];
                unsigned long long db = pack2(bv, bv);
                #pragma unroll
                for (int i = 0; i < 4; i++)
                    acc[i][j] = ffma2(ar[i], db, acc[i][j]);
            }
        }
        __syncthreads();
    }

    // epilogue: d2 = q2[row] + b2[col] - 2*cross
    if (tid < Bb) {
        q2s[tid] = g_q2[l * BB + m0 + tid];
        b2s[tid] = (n0 + tid < NPTS) ? g_b2[(size_t)l * NPTS + n0 + tid] : 0.f;
    }
    __syncthreads();

    float* D = g_d2 + ((size_t)l * BB + m0) * NPTS + n0;
    #pragma unroll
    for (int i = 0; i < 4; i++) {
        int r0 = tm * 8 + 2 * i;
        float qa = q2s[r0];
        float qb = q2s[r0 + 1];
        #pragma unroll
        for (int j = 0; j < 8; j++) {
            int c = tn + 16 * j;
            if (c < nrem) {
                float ca, cb;
                unpack2(acc[i][j], ca, cb);
                float bt = b2s[c];
                float d2a = fmaxf(fmaf(-2.f, ca, qa + bt), 0.f);
                float d2b = fmaxf(fmaf(-2.f, cb, qb + bt), 0.f);
                D[(size_t)r0 * NPTS + c]       = d2a;
                D[(size_t)(r0 + 1) * NPTS + c] = d2b;
            }
        }
    }
}

// ============================================================
// Kernel 5: per-(l,b) 21 smallest d2 -> LID
//   out[b, l] = -k / sum_{i=2..21} 0.5*log(d2_(i)/d2_(21))
// ============================================================
__global__ __launch_bounds__(256)
void topk_lid_kernel(float* __restrict__ out) {
    const int row = blockIdx.x;          // l*BB + b
    const float* D = g_d2 + (size_t)row * NPTS;
    const int tid = threadIdx.x;
    const int lane = tid & 31;
    const int wid = tid >> 5;

    // per-thread sorted ascending top-21 (static indices only -> registers)
    float r[KSEL];
    #pragma unroll
    for (int i = 0; i < KSEL; i++) r[i] = FLT_MAX;

    for (int n = tid; n < NPTS; n += 256) {
        float v = D[n];
        if (v < r[KSEL - 1]) {
            #pragma unroll
            for (int j = KSEL - 1; j >= 1; j--)
                r[j] = (v < r[j - 1]) ? r[j - 1] : ((v < r[j]) ? v : r[j]);
            r[0] = (v < r[0]) ? v : r[0];
        }
    }

    __shared__ float cand[256 * KSEL];   // 21 KB
    __shared__ float wmin[8];
    __shared__ int   wloc[8];
    __shared__ float sel[KSEL];

    #pragma unroll
    for (int i = 0; i < KSEL; i++) cand[tid * KSEL + i] = r[i];
    __syncthreads();

    // 21 sequential global-min extractions (warp-shuffle reduction)
    for (int it = 0; it < KSEL; it++) {
        float mv = FLT_MAX; int mi = 0;
        #pragma unroll
        for (int i = 0; i < KSEL; i++) {
            float v = cand[tid * KSEL + i];
            if (v < mv) { mv = v; mi = tid * KSEL + i; }
        }
        // warp reduce (value + location)
        #pragma unroll
        for (int o = 16; o > 0; o >>= 1) {
            float ov = __shfl_xor_sync(0xFFFFFFFFu, mv, o);
            int   oi = __shfl_xor_sync(0xFFFFFFFFu, mi, o);
            if (ov < mv) { mv = ov; mi = oi; }
        }
        if (lane == 0) { wmin[wid] = mv; wloc[wid] = mi; }
        __syncthreads();
        if (tid == 0) {
            float gv = wmin[0]; int gi = wloc[0];
            #pragma unroll
            for (int w = 1; w < 8; w++)
                if (wmin[w] < gv) { gv = wmin[w]; gi = wloc[w]; }
            sel[it] = gv;
            cand[gi] = FLT_MAX;
        }
        __syncthreads();
    }

    if (tid == 0) {
        // sel[0] = d2_(1) (excluded), sel[1..20] = d2_(2..21), sel[20] = r_k^2
        float rk2 = sel[KSEL - 1];
        float s = 0.f;
        #pragma unroll
        for (int i = 1; i < KSEL - 1; i++)
            s += 0.5f * logf(sel[i] / rk2);
        // i = KSEL-1 term is log(1) = 0
        int l = row / BB;
        int b = row % BB;
        out[b * LL + l] = -(20.0f / s);
    }
}

// ============================================================
extern "C" void kernel_launch(void* const* d_in, const int* in_sizes, int n_in,
                              void* d_out, int out_size) {
    const float* feats = (const float*)d_in[0];
    const float* bank  = (const float*)d_in[1];
    // d_in[2] (k) is fixed at 20 for this problem.

    qmean_kernel<<<(LL * BB * CC) / 8, 256>>>(feats);       // 65536 blocks
    q2_kernel<<<(LL * BB + 7) / 8, 256>>>();
    b2_kernel<<<(LL * NPTS) / 8, 256>>>(bank);              // 25000 blocks

    dim3 gg(2, (NPTS + Bn - 1) / Bn, LL);                   // (2, 391, 4)
    gemm_d2_kernel<<<gg, 256>>>(bank);

    topk_lid_kernel<<<LL * BB, 256>>>((float*)d_out);
}

// round 5
// speedup vs baseline: 1.9119x; 1.9119x over previous
#include <cuda_runtime.h>
#include <math.h>
#include <float.h>
#include <stdint.h>

// Problem constants (fixed by the dataset)
#define LL 4
#define BB 256
#define CC 512
#define SS 64
#define NPTS 50000
#define KSEL 21   // k+1 smallest needed

// -------- scratch (static device globals; no runtime allocation) --------
__device__ float g_q[LL * BB * CC];            // 2 MB
__device__ float g_q2[LL * BB];
__device__ float g_d2[(size_t)LL * BB * NPTS]; // 204.8 MB

// ============================================================
// Kernel 1: q[l,b,c] = mean_s feats[l,b,c,s]   (one warp per row of 64)
// ============================================================
__global__ void qmean_kernel(const float* __restrict__ feats) {
    int gw = (blockIdx.x * blockDim.x + threadIdx.x) >> 5;
    int lane = threadIdx.x & 31;
    if (gw >= LL * BB * CC) return;
    const float* p = feats + (size_t)gw * SS;
    float s = p[lane] + p[lane + 32];
    #pragma unroll
    for (int o = 16; o > 0; o >>= 1) s += __shfl_xor_sync(0xFFFFFFFFu, s, o);
    if (lane == 0) g_q[gw] = s * (1.0f / 64.0f);
}

// ============================================================
// Kernel 2: q2[l,b] = sum_c q^2     (one warp per row of 512)
// ============================================================
__global__ void q2_kernel() {
    int gw = (blockIdx.x * blockDim.x + threadIdx.x) >> 5;
    int lane = threadIdx.x & 31;
    if (gw >= LL * BB) return;
    const float* p = g_q + (size_t)gw * CC;
    float s = 0.f;
    #pragma unroll
    for (int j = 0; j < CC / 32; j++) {
        float v = p[lane + 32 * j];
        s = fmaf(v, v, s);
    }
    #pragma unroll
    for (int o = 16; o > 0; o >>= 1) s += __shfl_xor_sync(0xFFFFFFFFu, s, o);
    if (lane == 0) g_q2[gw] = s;
}

// ============================================================
// mma.sync m16n8k8 tf32 helpers
// ============================================================
__device__ __forceinline__ uint32_t f2tf32(float f) {
    uint32_t r;
    asm("cvt.rna.tf32.f32 %0, %1;" : "=r"(r) : "f"(f));
    return r;
}
__device__ __forceinline__ void mma_tf32(float* c, const uint32_t* a, const uint32_t* b) {
    asm volatile(
        "mma.sync.aligned.m16n8k8.row.col.f32.tf32.tf32.f32 "
        "{%0,%1,%2,%3}, {%4,%5,%6,%7}, {%8,%9}, {%0,%1,%2,%3};"
        : "+f"(c[0]), "+f"(c[1]), "+f"(c[2]), "+f"(c[3])
        : "r"(a[0]), "r"(a[1]), "r"(a[2]), "r"(a[3]), "r"(b[0]), "r"(b[1]));
}

// ============================================================
// Kernel 3: tf32 mma GEMM + fused b2 + d2 epilogue
//   CTA tile: 128 q rows (m) x 128 bank rows (n), BK=16, 256 threads.
//   Warp grid 2(m) x 4(n); warp tile 64x32 = 4x4 mma tiles of m16n8k8.
//   d2[l,m,n] = q2[l,m] + b2[l,n] - 2*cross   (b2 computed in-flight)
// ============================================================
#define Bb 128
#define Bn 128
#define Bk 16
#define LDT 20   // smem row stride in 4B words (16 + 4 pad -> conflict-free frags)

__global__ __launch_bounds__(256)
void gemm_mma_kernel(const float* __restrict__ bank) {
    __shared__ uint32_t As[Bb * LDT];   // q tile,   [m][k] tf32 bits
    __shared__ uint32_t Bs[Bn * LDT];   // bank tile,[n][k] tf32 bits
    __shared__ float q2s[Bb];
    __shared__ float b2s[Bn];

    const int l  = blockIdx.z;
    const int m0 = blockIdx.x * Bb;   // 0 or 128 (q rows)
    const int n0 = blockIdx.y * Bn;   // bank tile
    const int nrem = NPTS - n0;

    const float* Ap = g_q  + ((size_t)l * BB   + m0) * CC;
    const float* Bp = bank + ((size_t)l * NPTS + n0) * CC;

    const int tid  = threadIdx.x;
    const int lane = tid & 31;
    const int wid  = tid >> 5;
    const int wm   = wid & 1;          // 2 m-blocks of 64
    const int wn   = wid >> 1;         // 4 n-blocks of 32
    const int gr   = lane >> 2;        // 0..7
    const int tg   = lane & 3;         // 0..3

    // loader mapping: row = tid>>2 (+64), k-quad = (tid&3)*4
    const int lrow = tid >> 2;
    const int lk4  = (tid & 3) * 4;
    const bool bok0 = (lrow      < nrem);
    const bool bok1 = (lrow + 64 < nrem);

    float c[4][4][4];
    #pragma unroll
    for (int i = 0; i < 4; i++)
        #pragma unroll
        for (int j = 0; j < 4; j++)
            #pragma unroll
            for (int t = 0; t < 4; t++) c[i][j][t] = 0.f;

    float ssq0 = 0.f, ssq1 = 0.f;

    for (int k0 = 0; k0 < CC; k0 += Bk) {
        // ---- A tile (q): 128 rows x 16 k ----
        #pragma unroll
        for (int i = 0; i < 2; i++) {
            int row = lrow + 64 * i;
            float4 v = *(const float4*)(Ap + (size_t)row * CC + k0 + lk4);
            uint4 u = make_uint4(f2tf32(v.x), f2tf32(v.y), f2tf32(v.z), f2tf32(v.w));
            *(uint4*)&As[row * LDT + lk4] = u;
        }
        // ---- B tile (bank): 128 rows x 16 k, fused ssq ----
        {
            float4 v = make_float4(0.f, 0.f, 0.f, 0.f);
            if (bok0) v = *(const float4*)(Bp + (size_t)lrow * CC + k0 + lk4);
            ssq0 = fmaf(v.x, v.x, ssq0); ssq0 = fmaf(v.y, v.y, ssq0);
            ssq0 = fmaf(v.z, v.z, ssq0); ssq0 = fmaf(v.w, v.w, ssq0);
            *(uint4*)&Bs[lrow * LDT + lk4] =
                make_uint4(f2tf32(v.x), f2tf32(v.y), f2tf32(v.z), f2tf32(v.w));

            float4 w = make_float4(0.f, 0.f, 0.f, 0.f);
            if (bok1) w = *(const float4*)(Bp + (size_t)(lrow + 64) * CC + k0 + lk4);
            ssq1 = fmaf(w.x, w.x, ssq1); ssq1 = fmaf(w.y, w.y, ssq1);
            ssq1 = fmaf(w.z, w.z, ssq1); ssq1 = fmaf(w.w, w.w, ssq1);
            *(uint4*)&Bs[(lrow + 64) * LDT + lk4] =
                make_uint4(f2tf32(w.x), f2tf32(w.y), f2tf32(w.z), f2tf32(w.w));
        }
        __syncthreads();

        #pragma unroll
        for (int ks = 0; ks < Bk; ks += 8) {
            uint32_t a[4][4], b[4][2];
            #pragma unroll
            for (int mt = 0; mt < 4; mt++) {
                int base = (wm * 64 + mt * 16 + gr) * LDT + ks + tg;
                a[mt][0] = As[base];
                a[mt][1] = As[base + 8 * LDT];
                a[mt][2] = As[base + 4];
                a[mt][3] = As[base + 8 * LDT + 4];
            }
            #pragma unroll
            for (int nt = 0; nt < 4; nt++) {
                int base = (wn * 32 + nt * 8 + gr) * LDT + ks + tg;
                b[nt][0] = Bs[base];
                b[nt][1] = Bs[base + 4];
            }
            #pragma unroll
            for (int mt = 0; mt < 4; mt++)
                #pragma unroll
                for (int nt = 0; nt < 4; nt++)
                    mma_tf32(c[mt][nt], a[mt], b[nt]);
        }
        __syncthreads();
    }

    // ---- b2: sum the 4 k-quarters within each 4-thread group ----
    ssq0 += __shfl_xor_sync(0xFFFFFFFFu, ssq0, 1);
    ssq0 += __shfl_xor_sync(0xFFFFFFFFu, ssq0, 2);
    ssq1 += __shfl_xor_sync(0xFFFFFFFFu, ssq1, 1);
    ssq1 += __shfl_xor_sync(0xFFFFFFFFu, ssq1, 2);
    if ((tid & 3) == 0) {
        b2s[lrow]      = ssq0;
        b2s[lrow + 64] = ssq1;
    }
    if (tid < Bb) q2s[tid] = g_q2[l * BB + m0 + tid];
    __syncthreads();

    // ---- epilogue: c frag rows = q(m), cols = bank(n); float2 stores ----
    #pragma unroll
    for (int mt = 0; mt < 4; mt++) {
        int ml = wm * 64 + mt * 16 + gr;      // local q row
        float q2a = q2s[ml];
        float q2b = q2s[ml + 8];
        #pragma unroll
        for (int nt = 0; nt < 4; nt++) {
            int nl = wn * 32 + nt * 8 + 2 * tg;   // local bank col (even)
            if (nl < nrem) {
                float b2x = b2s[nl];
                float b2y = b2s[nl + 1];
                float2 r0, r1;
                r0.x = fmaxf(fmaf(-2.f, c[mt][nt][0], q2a + b2x), 0.f);
                r0.y = fmaxf(fmaf(-2.f, c[mt][nt][1], q2a + b2y), 0.f);
                r1.x = fmaxf(fmaf(-2.f, c[mt][nt][2], q2b + b2x), 0.f);
                r1.y = fmaxf(fmaf(-2.f, c[mt][nt][3], q2b + b2y), 0.f);
                size_t base = ((size_t)l * BB + m0 + ml) * NPTS + n0 + nl;
                *(float2*)&g_d2[base]               = r0;
                *(float2*)&g_d2[base + 8 * NPTS]    = r1;
            }
        }
    }
}

// ============================================================
// Kernel 4: per-(l,b) 21 smallest d2 -> LID
// ============================================================
__global__ __launch_bounds__(256)
void topk_lid_kernel(float* __restrict__ out) {
    const int row = blockIdx.x;          // l*BB + b
    const float* D = g_d2 + (size_t)row * NPTS;
    const int tid = threadIdx.x;
    const int lane = tid & 31;
    const int wid = tid >> 5;

    float r[KSEL];
    #pragma unroll
    for (int i = 0; i < KSEL; i++) r[i] = FLT_MAX;

    for (int n = tid; n < NPTS; n += 256) {
        float v = D[n];
        if (v < r[KSEL - 1]) {
            #pragma unroll
            for (int j = KSEL - 1; j >= 1; j--)
                r[j] = (v < r[j - 1]) ? r[j - 1] : ((v < r[j]) ? v : r[j]);
            r[0] = (v < r[0]) ? v : r[0];
        }
    }

    __shared__ float cand[256 * KSEL];
    __shared__ float wmin[8];
    __shared__ int   wloc[8];
    __shared__ float sel[KSEL];

    #pragma unroll
    for (int i = 0; i < KSEL; i++) cand[tid * KSEL + i] = r[i];
    __syncthreads();

    for (int it = 0; it < KSEL; it++) {
        float mv = FLT_MAX; int mi = 0;
        #pragma unroll
        for (int i = 0; i < KSEL; i++) {
            float v = cand[tid * KSEL + i];
            if (v < mv) { mv = v; mi = tid * KSEL + i; }
        }
        #pragma unroll
        for (int o = 16; o > 0; o >>= 1) {
            float ov = __shfl_xor_sync(0xFFFFFFFFu, mv, o);
            int   oi = __shfl_xor_sync(0xFFFFFFFFu, mi, o);
            if (ov < mv) { mv = ov; mi = oi; }
        }
        if (lane == 0) { wmin[wid] = mv; wloc[wid] = mi; }
        __syncthreads();
        if (tid == 0) {
            float gv = wmin[0]; int gi = wloc[0];
            #pragma unroll
            for (int w = 1; w < 8; w++)
                if (wmin[w] < gv) { gv = wmin[w]; gi = wloc[w]; }
            sel[it] = gv;
            cand[gi] = FLT_MAX;
        }
        __syncthreads();
    }

    if (tid == 0) {
        float rk2 = sel[KSEL - 1];
        float s = 0.f;
        #pragma unroll
        for (int i = 1; i < KSEL - 1; i++)
            s += 0.5f * logf(sel[i] / rk2);
        int l = row / BB;
        int b = row % BB;
        out[b * LL + l] = -(20.0f / s);
    }
}

// ============================================================
extern "C" void kernel_launch(void* const* d_in, const int* in_sizes, int n_in,
                              void* d_out, int out_size) {
    const float* feats = (const float*)d_in[0];
    const float* bank  = (const float*)d_in[1];
    // d_in[2] (k) is fixed at 20 for this problem.

    qmean_kernel<<<(LL * BB * CC) / 8, 256>>>(feats);
    q2_kernel<<<(LL * BB + 7) / 8, 256>>>();

    dim3 gg(2, (NPTS + Bn - 1) / Bn, LL);   // (2, 391, 4)
    gemm_mma_kernel<<<gg, 256>>>(bank);

    topk_lid_kernel<<<LL * BB, 256>>>((float*)d_out);
}

// round 7
// speedup vs baseline: 2.3009x; 1.2035x over previous
#include <cuda_runtime.h>
#include <math.h>
#include <float.h>
#include <stdint.h>

// Problem constants (fixed by the dataset)
#define LL 4
#define BB 256
#define CC 512
#define SS 64
#define NPTS 50000
#define KSEL 21   // k+1 smallest needed

// -------- scratch (static device globals; no runtime allocation) --------
__device__ float g_q[LL * BB * CC];            // 2 MB
__device__ float g_q2[LL * BB];
__device__ float g_d2[(size_t)LL * BB * NPTS]; // 204.8 MB

// ============================================================
// Kernel 1: q[l,b,c] = mean_s feats[l,b,c,s]   (one warp per row of 64)
// ============================================================
__global__ void qmean_kernel(const float* __restrict__ feats) {
    int gw = (blockIdx.x * blockDim.x + threadIdx.x) >> 5;
    int lane = threadIdx.x & 31;
    if (gw >= LL * BB * CC) return;
    const float* p = feats + (size_t)gw * SS;
    float s = p[lane] + p[lane + 32];
    #pragma unroll
    for (int o = 16; o > 0; o >>= 1) s += __shfl_xor_sync(0xFFFFFFFFu, s, o);
    if (lane == 0) g_q[gw] = s * (1.0f / 64.0f);
}

// ============================================================
// Kernel 2: q2[l,b] = sum_c q^2     (one warp per row of 512)
// ============================================================
__global__ void q2_kernel() {
    int gw = (blockIdx.x * blockDim.x + threadIdx.x) >> 5;
    int lane = threadIdx.x & 31;
    if (gw >= LL * BB) return;
    const float* p = g_q + (size_t)gw * CC;
    float s = 0.f;
    #pragma unroll
    for (int j = 0; j < CC / 32; j++) {
        float v = p[lane + 32 * j];
        s = fmaf(v, v, s);
    }
    #pragma unroll
    for (int o = 16; o > 0; o >>= 1) s += __shfl_xor_sync(0xFFFFFFFFu, s, o);
    if (lane == 0) g_q2[gw] = s;
}

// ============================================================
// mma.sync m16n8k8 tf32 helpers
// ============================================================
__device__ __forceinline__ uint32_t f2tf32(float f) {
    uint32_t r;
    asm("cvt.rna.tf32.f32 %0, %1;" : "=r"(r) : "f"(f));
    return r;
}
__device__ __forceinline__ void mma_tf32(float* c, const uint32_t* a, const uint32_t* b) {
    asm volatile(
        "mma.sync.aligned.m16n8k8.row.col.f32.tf32.tf32.f32 "
        "{%0,%1,%2,%3}, {%4,%5,%6,%7}, {%8,%9}, {%0,%1,%2,%3};"
        : "+f"(c[0]), "+f"(c[1]), "+f"(c[2]), "+f"(c[3])
        : "r"(a[0]), "r"(a[1]), "r"(a[2]), "r"(a[3]), "r"(b[0]), "r"(b[1]));
}

// ============================================================
// Kernel 3: tf32 mma GEMM + fused b2 + d2 epilogue (unchanged from R5)
// ============================================================
#define Bb 128
#define Bn 128
#define Bk 16
#define LDT 20   // smem row stride in 4B words (16 + 4 pad -> conflict-free frags)

__global__ __launch_bounds__(256)
void gemm_mma_kernel(const float* __restrict__ bank) {
    __shared__ uint32_t As[Bb * LDT];   // q tile,   [m][k] tf32 bits
    __shared__ uint32_t Bs[Bn * LDT];   // bank tile,[n][k] tf32 bits
    __shared__ float q2s[Bb];
    __shared__ float b2s[Bn];

    const int l  = blockIdx.z;
    const int m0 = blockIdx.x * Bb;
    const int n0 = blockIdx.y * Bn;
    const int nrem = NPTS - n0;

    const float* Ap = g_q  + ((size_t)l * BB   + m0) * CC;
    const float* Bp = bank + ((size_t)l * NPTS + n0) * CC;

    const int tid  = threadIdx.x;
    const int lane = tid & 31;
    const int wid  = tid >> 5;
    const int wm   = wid & 1;
    const int wn   = wid >> 1;
    const int gr   = lane >> 2;
    const int tg   = lane & 3;

    const int lrow = tid >> 2;
    const int lk4  = (tid & 3) * 4;
    const bool bok0 = (lrow      < nrem);
    const bool bok1 = (lrow + 64 < nrem);

    float c[4][4][4];
    #pragma unroll
    for (int i = 0; i < 4; i++)
        #pragma unroll
        for (int j = 0; j < 4; j++)
            #pragma unroll
            for (int t = 0; t < 4; t++) c[i][j][t] = 0.f;

    float ssq0 = 0.f, ssq1 = 0.f;

    for (int k0 = 0; k0 < CC; k0 += Bk) {
        #pragma unroll
        for (int i = 0; i < 2; i++) {
            int row = lrow + 64 * i;
            float4 v = *(const float4*)(Ap + (size_t)row * CC + k0 + lk4);
            uint4 u = make_uint4(f2tf32(v.x), f2tf32(v.y), f2tf32(v.z), f2tf32(v.w));
            *(uint4*)&As[row * LDT + lk4] = u;
        }
        {
            float4 v = make_float4(0.f, 0.f, 0.f, 0.f);
            if (bok0) v = *(const float4*)(Bp + (size_t)lrow * CC + k0 + lk4);
            ssq0 = fmaf(v.x, v.x, ssq0); ssq0 = fmaf(v.y, v.y, ssq0);
            ssq0 = fmaf(v.z, v.z, ssq0); ssq0 = fmaf(v.w, v.w, ssq0);
            *(uint4*)&Bs[lrow * LDT + lk4] =
                make_uint4(f2tf32(v.x), f2tf32(v.y), f2tf32(v.z), f2tf32(v.w));

            float4 w = make_float4(0.f, 0.f, 0.f, 0.f);
            if (bok1) w = *(const float4*)(Bp + (size_t)(lrow + 64) * CC + k0 + lk4);
            ssq1 = fmaf(w.x, w.x, ssq1); ssq1 = fmaf(w.y, w.y, ssq1);
            ssq1 = fmaf(w.z, w.z, ssq1); ssq1 = fmaf(w.w, w.w, ssq1);
            *(uint4*)&Bs[(lrow + 64) * LDT + lk4] =
                make_uint4(f2tf32(w.x), f2tf32(w.y), f2tf32(w.z), f2tf32(w.w));
        }
        __syncthreads();

        #pragma unroll
        for (int ks = 0; ks < Bk; ks += 8) {
            uint32_t a[4][4], b[4][2];
            #pragma unroll
            for (int mt = 0; mt < 4; mt++) {
                int base = (wm * 64 + mt * 16 + gr) * LDT + ks + tg;
                a[mt][0] = As[base];
                a[mt][1] = As[base + 8 * LDT];
                a[mt][2] = As[base + 4];
                a[mt][3] = As[base + 8 * LDT + 4];
            }
            #pragma unroll
            for (int nt = 0; nt < 4; nt++) {
                int base = (wn * 32 + nt * 8 + gr) * LDT + ks + tg;
                b[nt][0] = Bs[base];
                b[nt][1] = Bs[base + 4];
            }
            #pragma unroll
            for (int mt = 0; mt < 4; mt++)
                #pragma unroll
                for (int nt = 0; nt < 4; nt++)
                    mma_tf32(c[mt][nt], a[mt], b[nt]);
        }
        __syncthreads();
    }

    ssq0 += __shfl_xor_sync(0xFFFFFFFFu, ssq0, 1);
    ssq0 += __shfl_xor_sync(0xFFFFFFFFu, ssq0, 2);
    ssq1 += __shfl_xor_sync(0xFFFFFFFFu, ssq1, 1);
    ssq1 += __shfl_xor_sync(0xFFFFFFFFu, ssq1, 2);
    if ((tid & 3) == 0) {
        b2s[lrow]      = ssq0;
        b2s[lrow + 64] = ssq1;
    }
    if (tid < Bb) q2s[tid] = g_q2[l * BB + m0 + tid];
    __syncthreads();

    #pragma unroll
    for (int mt = 0; mt < 4; mt++) {
        int ml = wm * 64 + mt * 16 + gr;
        float q2a = q2s[ml];
        float q2b = q2s[ml + 8];
        #pragma unroll
        for (int nt = 0; nt < 4; nt++) {
            int nl = wn * 32 + nt * 8 + 2 * tg;
            if (nl < nrem) {
                float b2x = b2s[nl];
                float b2y = b2s[nl + 1];
                float2 r0, r1;
                r0.x = fmaxf(fmaf(-2.f, c[mt][nt][0], q2a + b2x), 0.f);
                r0.y = fmaxf(fmaf(-2.f, c[mt][nt][1], q2a + b2y), 0.f);
                r1.x = fmaxf(fmaf(-2.f, c[mt][nt][2], q2b + b2x), 0.f);
                r1.y = fmaxf(fmaf(-2.f, c[mt][nt][3], q2b + b2y), 0.f);
                size_t base = ((size_t)l * BB + m0 + ml) * NPTS + n0 + nl;
                *(float2*)&g_d2[base]               = r0;
                *(float2*)&g_d2[base + 8 * NPTS]    = r1;
            }
        }
    }
}

// ============================================================
// Kernel 4: per-(l,b) top-21 via threshold-gated candidate buffer
// ============================================================
#define CAP 11776          // candidate buffer capacity (46 KB, fits 48 KB static)
#define NF4 (NPTS / 4)     // 12500 float4 per row
#define SEEDF4 128         // first 512 elements seed the threshold

__global__ __launch_bounds__(256)
void topk_lid_kernel(float* __restrict__ out) {
    const int row = blockIdx.x;          // l*BB + b
    const float4* D4 = (const float4*)(g_d2 + (size_t)row * NPTS);
    const int tid = threadIdx.x;
    const int lane = tid & 31;
    const int wid = tid >> 5;

    __shared__ float buf[CAP + 32];
    __shared__ float sel[KSEL];
    __shared__ float wmin[8];
    __shared__ int   wloc[8];
    __shared__ int   cnt;
    __shared__ float tau;

    if (tid < KSEL) sel[tid] = FLT_MAX;
    if (tid == 0) cnt = 0;
    __syncthreads();

    // ---- merge lambda: select 21 smallest of (buf[0..cnt) U sel), set tau ----
    auto merge = [&]() {
        int c = cnt;
        if (tid < KSEL) buf[c + tid] = sel[tid];
        __syncthreads();
        int total = c + KSEL;
        for (int it = 0; it < KSEL; it++) {
            float mv = FLT_MAX; int mi = 0;
            for (int i = tid; i < total; i += 256) {
                float v = buf[i];
                if (v < mv) { mv = v; mi = i; }
            }
            #pragma unroll
            for (int o = 16; o > 0; o >>= 1) {
                float ov = __shfl_xor_sync(0xFFFFFFFFu, mv, o);
                int   oi = __shfl_xor_sync(0xFFFFFFFFu, mi, o);
                if (ov < mv) { mv = ov; mi = oi; }
            }
            if (lane == 0) { wmin[wid] = mv; wloc[wid] = mi; }
            __syncthreads();
            if (tid == 0) {
                float gv = wmin[0]; int gi = wloc[0];
                #pragma unroll
                for (int w = 1; w < 8; w++)
                    if (wmin[w] < gv) { gv = wmin[w]; gi = wloc[w]; }
                sel[it] = gv;
                buf[gi] = FLT_MAX;
            }
            __syncthreads();
        }
        if (tid == 0) { tau = sel[KSEL - 1]; cnt = 0; }
        __syncthreads();
    };

    // ---- seed: first 512 elements ----
    if (tid < SEEDF4) {
        float4 v = D4[tid];
        buf[tid * 4 + 0] = v.x;
        buf[tid * 4 + 1] = v.y;
        buf[tid * 4 + 2] = v.z;
        buf[tid * 4 + 3] = v.w;
    }
    if (tid == 0) cnt = SEEDF4 * 4;
    __syncthreads();
    merge();
    float tauR = tau;

    // ---- scan rest in chunks of 2048 float4 (8192 elements) ----
    int base = SEEDF4;
    bool first_chunk = true;
    while (base < NF4) {
        int end = base + 2048;
        if (end > NF4) end = NF4;
        for (int i = base + tid; i < end; i += 256) {
            float4 v = D4[i];
            if (v.x < tauR) { int p = atomicAdd(&cnt, 1); buf[p] = v.x; }
            if (v.y < tauR) { int p = atomicAdd(&cnt, 1); buf[p] = v.y; }
            if (v.z < tauR) { int p = atomicAdd(&cnt, 1); buf[p] = v.z; }
            if (v.w < tauR) { int p = atomicAdd(&cnt, 1); buf[p] = v.w; }
        }
        __syncthreads();
        // tighten tau after first chunk; otherwise only on overflow risk
        if ((first_chunk && cnt > 0) || cnt >= CAP - 8192) {
            merge();
        }
        tauR = tau;
        first_chunk = false;
        base = end;
    }
    if (cnt > 0) merge();

    // ---- LID from sel[0..20] (ascending d2) ----
    if (tid == 0) {
        float rk2 = sel[KSEL - 1];
        float s = 0.f;
        #pragma unroll
        for (int i = 1; i < KSEL - 1; i++)
            s += 0.5f * logf(sel[i] / rk2);
        int l = row / BB;
        int b = row % BB;
        out[b * LL + l] = -(20.0f / s);
    }
}

// ============================================================
extern "C" void kernel_launch(void* const* d_in, const int* in_sizes, int n_in,
                              void* d_out, int out_size) {
    const float* feats = (const float*)d_in[0];
    const float* bank  = (const float*)d_in[1];
    // d_in[2] (k) is fixed at 20 for this problem.

    qmean_kernel<<<(LL * BB * CC) / 8, 256>>>(feats);
    q2_kernel<<<(LL * BB + 7) / 8, 256>>>();

    dim3 gg(2, (NPTS + Bn - 1) / Bn, LL);   // (2, 391, 4)
    gemm_mma_kernel<<<gg, 256>>>(bank);

    topk_lid_kernel<<<LL * BB, 256>>>((float*)d_out);
}

// round 8
// speedup vs baseline: 2.6204x; 1.1389x over previous
#include <cuda_runtime.h>
#include <math.h>
#include <float.h>
#include <stdint.h>

// Problem constants (fixed by the dataset)
#define LL 4
#define BB 256
#define CC 512
#define SS 64
#define NPTS 50000
#define KSEL 21   // k+1 smallest needed

// -------- scratch (static device globals; no runtime allocation) --------
__device__ float g_q[LL * BB * CC];            // 2 MB
__device__ float g_q2[LL * BB];
__device__ float g_d2[(size_t)LL * BB * NPTS]; // 204.8 MB

// ============================================================
// Kernel 1: q[l,b,c] = mean_s feats[l,b,c,s]   (one warp per row of 64)
// ============================================================
__global__ void qmean_kernel(const float* __restrict__ feats) {
    int gw = (blockIdx.x * blockDim.x + threadIdx.x) >> 5;
    int lane = threadIdx.x & 31;
    if (gw >= LL * BB * CC) return;
    const float* p = feats + (size_t)gw * SS;
    float s = p[lane] + p[lane + 32];
    #pragma unroll
    for (int o = 16; o > 0; o >>= 1) s += __shfl_xor_sync(0xFFFFFFFFu, s, o);
    if (lane == 0) g_q[gw] = s * (1.0f / 64.0f);
}

// ============================================================
// Kernel 2: q2[l,b] = sum_c q^2     (one warp per row of 512)
// ============================================================
__global__ void q2_kernel() {
    int gw = (blockIdx.x * blockDim.x + threadIdx.x) >> 5;
    int lane = threadIdx.x & 31;
    if (gw >= LL * BB) return;
    const float* p = g_q + (size_t)gw * CC;
    float s = 0.f;
    #pragma unroll
    for (int j = 0; j < CC / 32; j++) {
        float v = p[lane + 32 * j];
        s = fmaf(v, v, s);
    }
    #pragma unroll
    for (int o = 16; o > 0; o >>= 1) s += __shfl_xor_sync(0xFFFFFFFFu, s, o);
    if (lane == 0) g_q2[gw] = s;
}

// ============================================================
// mma.sync m16n8k8 tf32 helpers
// ============================================================
__device__ __forceinline__ uint32_t f2tf32(float f) {
    uint32_t r;
    asm("cvt.rna.tf32.f32 %0, %1;" : "=r"(r) : "f"(f));
    return r;
}
__device__ __forceinline__ void mma_tf32(float* c, const uint32_t* a, const uint32_t* b) {
    asm volatile(
        "mma.sync.aligned.m16n8k8.row.col.f32.tf32.tf32.f32 "
        "{%0,%1,%2,%3}, {%4,%5,%6,%7}, {%8,%9}, {%0,%1,%2,%3};"
        : "+f"(c[0]), "+f"(c[1]), "+f"(c[2]), "+f"(c[3])
        : "r"(a[0]), "r"(a[1]), "r"(a[2]), "r"(a[3]), "r"(b[0]), "r"(b[1]));
}

// ============================================================
// Kernel 3: tf32 mma GEMM + fused b2 + d2 epilogue
//   Register-prefetch pipelined: next tile's LDGs issued before the
//   mma block so DRAM latency overlaps tensor work.
// ============================================================
#define Bb 128
#define Bn 128
#define Bk 16
#define LDT 20   // smem row stride in 4B words (16 + 4 pad -> conflict-free frags)

__global__ __launch_bounds__(256)
void gemm_mma_kernel(const float* __restrict__ bank) {
    __shared__ uint32_t As[Bb * LDT];   // q tile,   [m][k] tf32 bits
    __shared__ uint32_t Bs[Bn * LDT];   // bank tile,[n][k] tf32 bits
    __shared__ float q2s[Bb];
    __shared__ float b2s[Bn];

    const int l  = blockIdx.z;
    const int m0 = blockIdx.x * Bb;
    const int n0 = blockIdx.y * Bn;
    const int nrem = NPTS - n0;

    const float* Ap = g_q  + ((size_t)l * BB   + m0) * CC;
    const float* Bp = bank + ((size_t)l * NPTS + n0) * CC;

    const int tid  = threadIdx.x;
    const int lane = tid & 31;
    const int wid  = tid >> 5;
    const int wm   = wid & 1;
    const int wn   = wid >> 1;
    const int gr   = lane >> 2;
    const int tg   = lane & 3;

    const int lrow = tid >> 2;
    const int lk4  = (tid & 3) * 4;
    const bool bok0 = (lrow      < nrem);
    const bool bok1 = (lrow + 64 < nrem);

    const float* ap0 = Ap + (size_t)lrow * CC + lk4;
    const float* ap1 = Ap + (size_t)(lrow + 64) * CC + lk4;
    const float* bp0 = Bp + (size_t)lrow * CC + lk4;
    const float* bp1 = Bp + (size_t)(lrow + 64) * CC + lk4;

    float c[4][4][4];
    #pragma unroll
    for (int i = 0; i < 4; i++)
        #pragma unroll
        for (int j = 0; j < 4; j++)
            #pragma unroll
            for (int t = 0; t < 4; t++) c[i][j][t] = 0.f;

    float ssq0 = 0.f, ssq1 = 0.f;
    const float4 z4 = make_float4(0.f, 0.f, 0.f, 0.f);

    // ---- prologue: load tile 0 into regs, commit to smem ----
    float4 pa0 = *(const float4*)(ap0);
    float4 pa1 = *(const float4*)(ap1);
    float4 pb0 = bok0 ? *(const float4*)(bp0) : z4;
    float4 pb1 = bok1 ? *(const float4*)(bp1) : z4;

    {
        *(uint4*)&As[lrow * LDT + lk4] =
            make_uint4(f2tf32(pa0.x), f2tf32(pa0.y), f2tf32(pa0.z), f2tf32(pa0.w));
        *(uint4*)&As[(lrow + 64) * LDT + lk4] =
            make_uint4(f2tf32(pa1.x), f2tf32(pa1.y), f2tf32(pa1.z), f2tf32(pa1.w));
        ssq0 = fmaf(pb0.x, pb0.x, ssq0); ssq0 = fmaf(pb0.y, pb0.y, ssq0);
        ssq0 = fmaf(pb0.z, pb0.z, ssq0); ssq0 = fmaf(pb0.w, pb0.w, ssq0);
        *(uint4*)&Bs[lrow * LDT + lk4] =
            make_uint4(f2tf32(pb0.x), f2tf32(pb0.y), f2tf32(pb0.z), f2tf32(pb0.w));
        ssq1 = fmaf(pb1.x, pb1.x, ssq1); ssq1 = fmaf(pb1.y, pb1.y, ssq1);
        ssq1 = fmaf(pb1.z, pb1.z, ssq1); ssq1 = fmaf(pb1.w, pb1.w, ssq1);
        *(uint4*)&Bs[(lrow + 64) * LDT + lk4] =
            make_uint4(f2tf32(pb1.x), f2tf32(pb1.y), f2tf32(pb1.z), f2tf32(pb1.w));
    }
    __syncthreads();

    #pragma unroll 1
    for (int k0 = 0; k0 < CC; k0 += Bk) {
        const int kn = k0 + Bk;
        const bool have_next = (kn < CC);
        // ---- prefetch next tile into registers (overlaps with mma) ----
        if (have_next) {
            pa0 = *(const float4*)(ap0 + kn);
            pa1 = *(const float4*)(ap1 + kn);
            pb0 = bok0 ? *(const float4*)(bp0 + kn) : z4;
            pb1 = bok1 ? *(const float4*)(bp1 + kn) : z4;
        }

        // ---- mma on current smem tiles ----
        #pragma unroll
        for (int ks = 0; ks < Bk; ks += 8) {
            uint32_t a[4][4], b[4][2];
            #pragma unroll
            for (int mt = 0; mt < 4; mt++) {
                int base = (wm * 64 + mt * 16 + gr) * LDT + ks + tg;
                a[mt][0] = As[base];
                a[mt][1] = As[base + 8 * LDT];
                a[mt][2] = As[base + 4];
                a[mt][3] = As[base + 8 * LDT + 4];
            }
            #pragma unroll
            for (int nt = 0; nt < 4; nt++) {
                int base = (wn * 32 + nt * 8 + gr) * LDT + ks + tg;
                b[nt][0] = Bs[base];
                b[nt][1] = Bs[base + 4];
            }
            #pragma unroll
            for (int mt = 0; mt < 4; mt++)
                #pragma unroll
                for (int nt = 0; nt < 4; nt++)
                    mma_tf32(c[mt][nt], a[mt], b[nt]);
        }
        __syncthreads();

        // ---- commit prefetched tile to smem ----
        if (have_next) {
            *(uint4*)&As[lrow * LDT + lk4] =
                make_uint4(f2tf32(pa0.x), f2tf32(pa0.y), f2tf32(pa0.z), f2tf32(pa0.w));
            *(uint4*)&As[(lrow + 64) * LDT + lk4] =
                make_uint4(f2tf32(pa1.x), f2tf32(pa1.y), f2tf32(pa1.z), f2tf32(pa1.w));
            ssq0 = fmaf(pb0.x, pb0.x, ssq0); ssq0 = fmaf(pb0.y, pb0.y, ssq0);
            ssq0 = fmaf(pb0.z, pb0.z, ssq0); ssq0 = fmaf(pb0.w, pb0.w, ssq0);
            *(uint4*)&Bs[lrow * LDT + lk4] =
                make_uint4(f2tf32(pb0.x), f2tf32(pb0.y), f2tf32(pb0.z), f2tf32(pb0.w));
            ssq1 = fmaf(pb1.x, pb1.x, ssq1); ssq1 = fmaf(pb1.y, pb1.y, ssq1);
            ssq1 = fmaf(pb1.z, pb1.z, ssq1); ssq1 = fmaf(pb1.w, pb1.w, ssq1);
            *(uint4*)&Bs[(lrow + 64) * LDT + lk4] =
                make_uint4(f2tf32(pb1.x), f2tf32(pb1.y), f2tf32(pb1.z), f2tf32(pb1.w));
            __syncthreads();
        }
    }

    // ---- b2 reduce ----
    ssq0 += __shfl_xor_sync(0xFFFFFFFFu, ssq0, 1);
    ssq0 += __shfl_xor_sync(0xFFFFFFFFu, ssq0, 2);
    ssq1 += __shfl_xor_sync(0xFFFFFFFFu, ssq1, 1);
    ssq1 += __shfl_xor_sync(0xFFFFFFFFu, ssq1, 2);
    __syncthreads();     // all mma reads of Bs/As done before reuse below
    if ((tid & 3) == 0) {
        b2s[lrow]      = ssq0;
        b2s[lrow + 64] = ssq1;
    }
    if (tid < Bb) q2s[tid] = g_q2[l * BB + m0 + tid];
    __syncthreads();

    // ---- epilogue ----
    #pragma unroll
    for (int mt = 0; mt < 4; mt++) {
        int ml = wm * 64 + mt * 16 + gr;
        float q2a = q2s[ml];
        float q2b = q2s[ml + 8];
        #pragma unroll
        for (int nt = 0; nt < 4; nt++) {
            int nl = wn * 32 + nt * 8 + 2 * tg;
            if (nl < nrem) {
                float b2x = b2s[nl];
                float b2y = b2s[nl + 1];
                float2 r0, r1;
                r0.x = fmaxf(fmaf(-2.f, c[mt][nt][0], q2a + b2x), 0.f);
                r0.y = fmaxf(fmaf(-2.f, c[mt][nt][1], q2a + b2y), 0.f);
                r1.x = fmaxf(fmaf(-2.f, c[mt][nt][2], q2b + b2x), 0.f);
                r1.y = fmaxf(fmaf(-2.f, c[mt][nt][3], q2b + b2y), 0.f);
                size_t base = ((size_t)l * BB + m0 + ml) * NPTS + n0 + nl;
                *(float2*)&g_d2[base]               = r0;
                *(float2*)&g_d2[base + 8 * NPTS]    = r1;
            }
        }
    }
}

// ============================================================
// Kernel 4: per-(l,b) top-21 via threshold-gated candidate buffer
//   CAP shrunk to 6144 (25 KB) -> ~1 wave of 1024 CTAs; scan with
//   4 outstanding LDG.128 per thread per chunk (MLP=4).
// ============================================================
#define CAP 6144           // candidate buffer capacity (24 KB)
#define NF4 (NPTS / 4)     // 12500 float4 per row
#define SEEDF4 128         // first 512 elements seed the threshold
#define CHUNKF4 1024       // 4096 elements per chunk = 4 float4/thread

__global__ __launch_bounds__(256)
void topk_lid_kernel(float* __restrict__ out) {
    const int row = blockIdx.x;          // l*BB + b
    const float4* D4 = (const float4*)(g_d2 + (size_t)row * NPTS);
    const int tid = threadIdx.x;
    const int lane = tid & 31;
    const int wid = tid >> 5;

    __shared__ float buf[CAP + 32];
    __shared__ float sel[KSEL];
    __shared__ float wmin[8];
    __shared__ int   wloc[8];
    __shared__ int   cnt;
    __shared__ float tau;

    if (tid < KSEL) sel[tid] = FLT_MAX;
    if (tid == 0) cnt = 0;
    __syncthreads();

    auto merge = [&]() {
        int c = cnt;
        if (tid < KSEL) buf[c + tid] = sel[tid];
        __syncthreads();
        int total = c + KSEL;
        for (int it = 0; it < KSEL; it++) {
            float mv = FLT_MAX; int mi = 0;
            for (int i = tid; i < total; i += 256) {
                float v = buf[i];
                if (v < mv) { mv = v; mi = i; }
            }
            #pragma unroll
            for (int o = 16; o > 0; o >>= 1) {
                float ov = __shfl_xor_sync(0xFFFFFFFFu, mv, o);
                int   oi = __shfl_xor_sync(0xFFFFFFFFu, mi, o);
                if (ov < mv) { mv = ov; mi = oi; }
            }
            if (lane == 0) { wmin[wid] = mv; wloc[wid] = mi; }
            __syncthreads();
            if (tid == 0) {
                float gv = wmin[0]; int gi = wloc[0];
                #pragma unroll
                for (int w = 1; w < 8; w++)
                    if (wmin[w] < gv) { gv = wmin[w]; gi = wloc[w]; }
                sel[it] = gv;
                buf[gi] = FLT_MAX;
            }
            __syncthreads();
        }
        if (tid == 0) { tau = sel[KSEL - 1]; cnt = 0; }
        __syncthreads();
    };

    // ---- seed: first 512 elements ----
    if (tid < SEEDF4) {
        float4 v = D4[tid];
        buf[tid * 4 + 0] = v.x;
        buf[tid * 4 + 1] = v.y;
        buf[tid * 4 + 2] = v.z;
        buf[tid * 4 + 3] = v.w;
    }
    if (tid == 0) cnt = SEEDF4 * 4;
    __syncthreads();
    merge();
    float tauR = tau;

    // ---- scan rest: chunks of 1024 float4, 4 LDG.128 in flight/thread ----
    int base = SEEDF4;
    bool first_chunk = true;
    while (base < NF4) {
        int end = base + CHUNKF4;
        if (end > NF4) end = NF4;
        int i = base + tid;
        // full quad (4 loads in flight)
        for (; i + 768 < end; i += 1024) {
            float4 v0 = D4[i];
            float4 v1 = D4[i + 256];
            float4 v2 = D4[i + 512];
            float4 v3 = D4[i + 768];
            if (v0.x < tauR) { int p = atomicAdd(&cnt, 1); buf[p] = v0.x; }
            if (v0.y < tauR) { int p = atomicAdd(&cnt, 1); buf[p] = v0.y; }
            if (v0.z < tauR) { int p = atomicAdd(&cnt, 1); buf[p] = v0.z; }
            if (v0.w < tauR) { int p = atomicAdd(&cnt, 1); buf[p] = v0.w; }
            if (v1.x < tauR) { int p = atomicAdd(&cnt, 1); buf[p] = v1.x; }
            if (v1.y < tauR) { int p = atomicAdd(&cnt, 1); buf[p] = v1.y; }
            if (v1.z < tauR) { int p = atomicAdd(&cnt, 1); buf[p] = v1.z; }
            if (v1.w < tauR) { int p = atomicAdd(&cnt, 1); buf[p] = v1.w; }
            if (v2.x < tauR) { int p = atomicAdd(&cnt, 1); buf[p] = v2.x; }
            if (v2.y < tauR) { int p = atomicAdd(&cnt, 1); buf[p] = v2.y; }
            if (v2.z < tauR) { int p = atomicAdd(&cnt, 1); buf[p] = v2.z; }
            if (v2.w < tauR) { int p = atomicAdd(&cnt, 1); buf[p] = v2.w; }
            if (v3.x < tauR) { int p = atomicAdd(&cnt, 1); buf[p] = v3.x; }
            if (v3.y < tauR) { int p = atomicAdd(&cnt, 1); buf[p] = v3.y; }
            if (v3.z < tauR) { int p = atomicAdd(&cnt, 1); buf[p] = v3.z; }
            if (v3.w < tauR) { int p = atomicAdd(&cnt, 1); buf[p] = v3.w; }
        }
        // remainder
        for (; i < end; i += 256) {
            float4 v = D4[i];
            if (v.x < tauR) { int p = atomicAdd(&cnt, 1); buf[p] = v.x; }
            if (v.y < tauR) { int p = atomicAdd(&cnt, 1); buf[p] = v.y; }
            if (v.z < tauR) { int p = atomicAdd(&cnt, 1); buf[p] = v.z; }
            if (v.w < tauR) { int p = atomicAdd(&cnt, 1); buf[p] = v.w; }
        }
        __syncthreads();
        // tighten tau after first chunk; otherwise only on overflow risk
        if ((first_chunk && cnt > 0) || cnt >= CAP - 4096) {
            merge();
        }
        tauR = tau;
        first_chunk = false;
        base = end;
    }
    if (cnt > 0) merge();

    // ---- LID ----
    if (tid == 0) {
        float rk2 = sel[KSEL - 1];
        float s = 0.f;
        #pragma unroll
        for (int i = 1; i < KSEL - 1; i++)
            s += 0.5f * logf(sel[i] / rk2);
        int l = row / BB;
        int b = row % BB;
        out[b * LL + l] = -(20.0f / s);
    }
}

// ============================================================
extern "C" void kernel_launch(void* const* d_in, const int* in_sizes, int n_in,
                              void* d_out, int out_size) {
    const float* feats = (const float*)d_in[0];
    const float* bank  = (const float*)d_in[1];
    // d_in[2] (k) is fixed at 20 for this problem.

    qmean_kernel<<<(LL * BB * CC) / 8, 256>>>(feats);
    q2_kernel<<<(LL * BB + 7) / 8, 256>>>();

    dim3 gg(2, (NPTS + Bn - 1) / Bn, LL);   // (2, 391, 4)
    gemm_mma_kernel<<<gg, 256>>>(bank);

    topk_lid_kernel<<<LL * BB, 256>>>((float*)d_out);
}